// round 16
// baseline (speedup 1.0000x reference)
#include <cuda_runtime.h>
#include <cuda_bf16.h>
#include <cuda_fp16.h>
#include <cstdint>

// Problem constants
#define BB   8
#define LL   1024
#define KNB  30
#define NUM_RBF 16
#define NPOS 16
#define MAXREL 32
#define EDGE 128
#define EDGE_IN (NPOS + NUM_RBF * 25)   // 416 = 26 * 16
#define NEDGE (BB * LL * KNB)           // 245760
#define E_ELEMS ((size_t)NEDGE * EDGE)  // 31457280
#define NKSTEP 26
#define WSCALE 32.0f                    // B pre-scale (avoids fp16 subnormals)
// LayerNorm is scale-invariant: fold 32^2 into eps instead of un-scaling acc.
#define LN_EPS_SCALED (1e-5f * 1024.0f)
#define RBF_A (-0.92332481f)            // -0.64 * log2(e)
#define RBF_D 1.33333337f

__constant__ int cPI[25] = {0,1,2,3,4,0,0,0,0,1,1,1,4,4,3,1,2,3,4,2,3,4,2,3,2};
__constant__ int cPJ[25] = {0,1,2,3,4,1,2,3,4,2,3,4,2,3,2,0,0,0,0,1,1,1,4,4,3};

// Scratch (static __device__ — no allocations allowed)
__device__ float4 g_atoms[BB * LL * 5];   // [Ca, N, C, O, Cb] per residue
__device__ float4 g_ca[BB * LL];
__device__ int    g_eidx[NEDGE];
// (W_edge*32)^T fp16: [n=128][k=416]  (row = 832 B = 52 uint4)
__device__ __align__(16) __half g_Bt[128 * 416];

// ---------------------------------------------------------------------------
// Small helpers
// ---------------------------------------------------------------------------
__device__ __forceinline__ uint32_t smem_u32(const void* p) {
    uint32_t a;
    asm("{ .reg .u64 t; cvta.to.shared.u64 t, %1; cvt.u32.u64 %0, t; }"
        : "=r"(a) : "l"(p));
    return a;
}
__device__ __forceinline__ uint32_t pack_f16x2(float f0, float f1) {
    uint32_t r;
    asm("cvt.rn.f16x2.f32 %0, %1, %2;" : "=r"(r) : "f"(f1), "f"(f0));
    return r;  // lo half = f0, hi half = f1
}
__device__ __forceinline__ float ex2f(float x) {
    float r;
    asm("ex2.approx.f32 %0, %1;" : "=f"(r) : "f"(x));
    return r;
}
__device__ __forceinline__ void mma16816(float* d, const uint32_t* a,
                                         const uint32_t* b) {
    asm volatile(
        "mma.sync.aligned.m16n8k16.row.col.f32.f16.f16.f32 "
        "{%0,%1,%2,%3}, {%4,%5,%6,%7}, {%8,%9}, {%0,%1,%2,%3};"
        : "+f"(d[0]), "+f"(d[1]), "+f"(d[2]), "+f"(d[3])
        : "r"(a[0]), "r"(a[1]), "r"(a[2]), "r"(a[3]), "r"(b[0]), "r"(b[1]));
}
__device__ __forceinline__ void ldsm4(uint32_t* r, uint32_t addr) {
    asm volatile(
        "ldmatrix.sync.aligned.m8n8.x4.shared.b16 {%0,%1,%2,%3}, [%4];"
        : "=r"(r[0]), "=r"(r[1]), "=r"(r[2]), "=r"(r[3]) : "r"(addr));
}
__device__ __forceinline__ unsigned long long kmin64(unsigned long long a,
                                                     unsigned long long b) {
    return a < b ? a : b;
}

// ---------------------------------------------------------------------------
// Kernel A (fused): prep (atom table) + bprep ((W*32)^T fp16).
// ---------------------------------------------------------------------------
__global__ void prep_fused_kernel(const float* __restrict__ X,
                                  const float* __restrict__ W_edge) {
    int idx = blockIdx.x * blockDim.x + threadIdx.x;
    if (idx < BB * LL) {
        int t = idx;
        const float* x = X + (size_t)t * 12;
        float Nx = x[0], Ny = x[1], Nz = x[2];
        float Ax = x[3], Ay = x[4], Az = x[5];
        float Cx = x[6], Cy = x[7], Cz = x[8];
        float Ox = x[9], Oy = x[10], Oz = x[11];
        float bx = Ax - Nx, by = Ay - Ny, bz = Az - Nz;
        float cx = Cx - Ax, cy = Cy - Ay, cz = Cz - Az;
        float ax = by * cz - bz * cy;
        float ay = bz * cx - bx * cz;
        float az = bx * cy - by * cx;
        float Bx = -0.58273431f * ax + 0.56802827f * bx - 0.54067466f * cx + Ax;
        float By = -0.58273431f * ay + 0.56802827f * by - 0.54067466f * cy + Ay;
        float Bz = -0.58273431f * az + 0.56802827f * bz - 0.54067466f * cz + Az;
        g_atoms[t * 5 + 0] = make_float4(Ax, Ay, Az, 0.f);
        g_atoms[t * 5 + 1] = make_float4(Nx, Ny, Nz, 0.f);
        g_atoms[t * 5 + 2] = make_float4(Cx, Cy, Cz, 0.f);
        g_atoms[t * 5 + 3] = make_float4(Ox, Oy, Oz, 0.f);
        g_atoms[t * 5 + 4] = make_float4(Bx, By, Bz, 0.f);
        g_ca[t] = make_float4(Ax, Ay, Az, 0.f);
    } else {
        int w = idx - BB * LL;
        if (w < 128 * 416) {
            int n = w / 416;
            int k = w - n * 416;
            float v = W_edge[k * 128 + n] * WSCALE;
            g_Bt[(size_t)n * 416 + k] = __float2half_rn(v);
        }
    }
}

// ---------------------------------------------------------------------------
// Kernel B: top-30 nearest neighbors (exact JAX tie-breaking).
// 4 rows per warp (4-way ILP on the serial shuffle chains).
// Hierarchical: register-resident 32 group minima per row; each round reduces
// the minima then rescans only the losing group.
// Keys bank-XOR-swizzled: element j at word (j & ~31) | ((j ^ (j>>5)) & 31).
// Dynamic smem: 16 rows * 1024 keys * 4 B = 64 KB.
// ---------------------------------------------------------------------------
__global__ void topk_kernel(float* __restrict__ idx_out_f, int write_idx_f) {
    extern __shared__ __align__(16) uint32_t tk_keys[];   // [16][LL]
    int tid = threadIdx.x;
    int warp = tid >> 5;
    int lane = tid & 31;
    int row0 = blockIdx.x * 16 + warp * 4;   // 4 rows, same batch
    int b = row0 >> 10;
    int base = b * LL;

    float4 cr[4];
    uint32_t* kr[4];
    #pragma unroll
    for (int r = 0; r < 4; r++) {
        cr[r] = g_ca[row0 + r];
        kr[r] = tk_keys + (warp * 4 + r) * LL;
    }

    // fill keys (swizzled), sharing the cj load across 4 rows
    #pragma unroll 2
    for (int c = 0; c < 32; c++) {
        int j = c * 32 + lane;
        float4 cj = g_ca[base + j];
        int sw = c * 32 + ((lane ^ c) & 31);
        #pragma unroll
        for (int r = 0; r < 4; r++) {
            float dx = cr[r].x - cj.x, dy = cr[r].y - cj.y, dz = cr[r].z - cj.z;
            kr[r][sw] = __float_as_uint(
                sqrtf(dx * dx + dy * dy + dz * dz + 1e-6f));
        }
    }
    __syncwarp();

    // group minima in registers: lane owns group g = lane
    unsigned long long gm[4];
    {
        uint32_t v[4] = {~0u, ~0u, ~0u, ~0u};
        int jj[4] = {0, 0, 0, 0};
        #pragma unroll 2
        for (int i = 0; i < 32; i++) {
            int sw = i * 32 + ((lane ^ i) & 31);
            int j = i * 32 + lane;
            #pragma unroll
            for (int r = 0; r < 4; r++) {
                uint32_t a = kr[r][sw];
                if (a < v[r]) { v[r] = a; jj[r] = j; }
            }
        }
        #pragma unroll
        for (int r = 0; r < 4; r++)
            gm[r] = ((unsigned long long)v[r] << 32) | (unsigned)jj[r];
    }

    for (int kk = 0; kk < KNB; kk++) {
        unsigned long long bb[4];
        #pragma unroll
        for (int r = 0; r < 4; r++) bb[r] = gm[r];
        #pragma unroll
        for (int off = 16; off; off >>= 1) {
            #pragma unroll
            for (int r = 0; r < 4; r++)
                bb[r] = kmin64(bb[r], __shfl_xor_sync(0xffffffffu, bb[r], off));
        }
        unsigned jw[4];
        #pragma unroll
        for (int r = 0; r < 4; r++) jw[r] = (unsigned)(bb[r] & 0xffffffffu);
        if (lane == 0) {
            #pragma unroll
            for (int r = 0; r < 4; r++) {
                g_eidx[(row0 + r) * KNB + kk] = (int)jw[r];
                if (write_idx_f)
                    idx_out_f[(row0 + r) * KNB + kk] = (float)jw[r];
                unsigned j = jw[r];
                kr[r][(j & ~31u) | ((j ^ (j >> 5)) & 31u)] = ~0u;
            }
        }
        __syncwarp();
        // rescan losing groups
        unsigned long long cd[4];
        #pragma unroll
        for (int r = 0; r < 4; r++) {
            int g = jw[r] & 31;
            uint32_t v = kr[r][lane * 32 + ((g ^ lane) & 31)];
            cd[r] = ((unsigned long long)v << 32) | (unsigned)(lane * 32 + g);
        }
        #pragma unroll
        for (int off = 16; off; off >>= 1) {
            #pragma unroll
            for (int r = 0; r < 4; r++)
                cd[r] = kmin64(cd[r], __shfl_xor_sync(0xffffffffu, cd[r], off));
        }
        #pragma unroll
        for (int r = 0; r < 4; r++)
            if (lane == (int)(jw[r] & 31)) gm[r] = cd[r];
        __syncwarp();
    }
}

// ---------------------------------------------------------------------------
// Kernel C: HMMA (mma.sync fp16) edge GEMM + LayerNorm.
// CTA: 512 threads / 16 warps in an 8(M)x2(N) grid, M=256 edges per CTA.
// Warp tile: M=32 (2 m16 tiles, B fragments reused) x N=64 (8 n8 tiles).
// Full B (K=416) resident in SMEM, row stride 848 B (conflict-free ldsm).
// RBF via canonical ex2 form: f = ex2(a*d^2 + b_k*d + c_k).
// SMEM: Bs[128 n][848 B rows]                                 108544
//       sdist[256][25] f32 (reused for LN reductions)          25600
//       spos [256][16] f32                                     16384
// ---------------------------------------------------------------------------
#define SM_BS   0
#define SM_DIST 108544
#define SM_POS  134144
#define SM_TOTAL 150528

__global__ __launch_bounds__(512, 1) void edge_hmma_kernel(
    const int* __restrict__ res_idx,
    const float* __restrict__ W_pos,
    const float* __restrict__ b_pos,
    const float* __restrict__ ln_gamma,
    const float* __restrict__ ln_beta,
    float* __restrict__ outE) {

    extern __shared__ __align__(16) char smem[];
    uint32_t sbase = smem_u32(smem);
    int tid = threadIdx.x;
    int wid = tid >> 5;
    int lane = tid & 31;
    int mw = wid >> 1;        // 0..7  -> M slice of 32
    int nw = wid & 1;         // 0..1  -> N slice of 64

    float* sdist = (float*)(smem + SM_DIST);
    float* spos  = (float*)(smem + SM_POS);

    // ---- load full B: 128 rows x 52 uint4 = 6656 = 512*13 ----
    {
        const uint4* src = (const uint4*)g_Bt;
        #pragma unroll
        for (int it = 0; it < 13; it++) {
            int idx = tid + it * 512;
            int n = idx / 52;
            int col = idx - n * 52;
            uint4 v = src[n * 52 + col];
            *(uint4*)(smem + SM_BS + n * 848 + col * 16) = v;
        }
    }

    // ---- per-edge setup (threads 0..255) ----
    if (tid < 256) {
        int e = blockIdx.x * 256 + tid;
        int row = e / KNB;
        int b = row >> 10;
        int j = g_eidx[e];
        float4 pa[5], pb[5];
        #pragma unroll
        for (int a = 0; a < 5; a++) {
            pa[a] = g_atoms[row * 5 + a];
            pb[a] = g_atoms[(b * LL + j) * 5 + a];
        }
        #pragma unroll
        for (int p = 0; p < 25; p++) {
            float4 u = pa[cPI[p]], v = pb[cPJ[p]];
            float dx = u.x - v.x, dy = u.y - v.y, dz = u.z - v.z;
            sdist[tid * 25 + p] = sqrtf(dx * dx + dy * dy + dz * dz + 1e-6f);
        }
        int off = res_idx[row] - res_idx[b * LL + j];
        int dpos = off + MAXREL;
        dpos = dpos < 0 ? 0 : (dpos > 2 * MAXREL ? 2 * MAXREL : dpos);
        #pragma unroll
        for (int t = 0; t < NPOS; t++)
            spos[tid * 16 + t] = W_pos[dpos * NPOS + t] + b_pos[t];
    }
    __syncthreads();

    // ---- per-lane constants for A-fragment feature generation ----
    int rq = lane >> 2;                    // 0..7
    int rbase = mw * 32 + rq;              // local edge row (mtile 0, first of pair)
    int cq = (lane & 3) * 2;               // k-col within kstep
    float mu0 = 2.0f + (float)cq * RBF_D;
    float mu1 = mu0 + RBF_D;
    float mu8 = mu0 + 8.0f * RBF_D;
    float mu9 = mu0 + 9.0f * RBF_D;
    float bb0 = -2.0f * RBF_A * mu0, cc0 = RBF_A * mu0 * mu0;
    float bb1 = -2.0f * RBF_A * mu1, cc1 = RBF_A * mu1 * mu1;
    float bb8 = -2.0f * RBF_A * mu8, cc8 = RBF_A * mu8 * mu8;
    float bb9 = -2.0f * RBF_A * mu9, cc9 = RBF_A * mu9 * mu9;

    // B fragment base: warp covers n rows [nw*64, nw*64+64)
    uint32_t b_base = sbase + SM_BS + (uint32_t)(nw * 64) * 848 +
        (uint32_t)((lane & 7) + ((lane >> 4) << 3)) * 848 +
        (uint32_t)((lane >> 3) & 1) * 16;

    float acc[64];   // [t(2)][nt(8)][4]
    #pragma unroll
    for (int i = 0; i < 64; i++) acc[i] = 0.f;

    // ---- ks = 0 peeled: pos features ----
    {
        uint32_t bh[16];
        #pragma unroll
        for (int g = 0; g < 4; g++)
            ldsm4(&bh[g * 4], b_base + g * 16 * 848);
        uint32_t ah[2][4];
        #pragma unroll
        for (int t = 0; t < 2; t++) {
            int eA = rbase + t * 16;
            int eB = eA + 8;
            ah[t][0] = pack_f16x2(spos[eA * 16 + cq],     spos[eA * 16 + cq + 1]);
            ah[t][1] = pack_f16x2(spos[eB * 16 + cq],     spos[eB * 16 + cq + 1]);
            ah[t][2] = pack_f16x2(spos[eA * 16 + cq + 8], spos[eA * 16 + cq + 9]);
            ah[t][3] = pack_f16x2(spos[eB * 16 + cq + 8], spos[eB * 16 + cq + 9]);
        }
        #pragma unroll
        for (int t = 0; t < 2; t++) {
            #pragma unroll
            for (int nt = 0; nt < 8; nt++)
                mma16816(&acc[(t * 8 + nt) * 4], ah[t],
                         &bh[(nt >> 1) * 4 + (nt & 1) * 2]);
        }
    }

    // ---- main K loop: ks = 1..25 (RBF features only) ----
    #pragma unroll 1
    for (int ks = 1; ks < NKSTEP; ks++) {
        uint32_t bh[16];
        uint32_t bks = b_base + (uint32_t)ks * 32;
        #pragma unroll
        for (int g = 0; g < 4; g++)
            ldsm4(&bh[g * 4], bks + g * 16 * 848);

        uint32_t ah[2][4];
        #pragma unroll
        for (int t = 0; t < 2; t++) {
            int eA = rbase + t * 16;
            int eB = eA + 8;
            float dA = sdist[eA * 25 + ks - 1];
            float dB = sdist[eB * 25 + ks - 1];
            float dA2 = dA * dA;
            float dB2 = dB * dB;
            float f0 = ex2f(fmaf(RBF_A, dA2, fmaf(bb0, dA, cc0)));
            float f1 = ex2f(fmaf(RBF_A, dA2, fmaf(bb1, dA, cc1)));
            float f2 = ex2f(fmaf(RBF_A, dB2, fmaf(bb0, dB, cc0)));
            float f3 = ex2f(fmaf(RBF_A, dB2, fmaf(bb1, dB, cc1)));
            float f4 = ex2f(fmaf(RBF_A, dA2, fmaf(bb8, dA, cc8)));
            float f5 = ex2f(fmaf(RBF_A, dA2, fmaf(bb9, dA, cc9)));
            float f6 = ex2f(fmaf(RBF_A, dB2, fmaf(bb8, dB, cc8)));
            float f7 = ex2f(fmaf(RBF_A, dB2, fmaf(bb9, dB, cc9)));
            ah[t][0] = pack_f16x2(f0, f1);
            ah[t][1] = pack_f16x2(f2, f3);
            ah[t][2] = pack_f16x2(f4, f5);
            ah[t][3] = pack_f16x2(f6, f7);
        }

        #pragma unroll
        for (int t = 0; t < 2; t++) {
            #pragma unroll
            for (int nt = 0; nt < 8; nt++)
                mma16816(&acc[(t * 8 + nt) * 4], ah[t],
                         &bh[(nt >> 1) * 4 + (nt & 1) * 2]);
        }
    }

    // ---- LayerNorm epilogue (scale-invariant: 32x fold into eps) ----
    __syncthreads();   // protect sdist reuse
    float* red1 = (float*)(smem + SM_DIST);          // [256][2] sums
    float* red2 = (float*)(smem + SM_DIST + 2048);   // [256][2] sq-sums

    // pass 1: sums
    #pragma unroll
    for (int t = 0; t < 2; t++) {
        float s1 = 0.f, s2 = 0.f;
        #pragma unroll
        for (int nt = 0; nt < 8; nt++) {
            const float* a4 = &acc[(t * 8 + nt) * 4];
            s1 += a4[0] + a4[1];
            s2 += a4[2] + a4[3];
        }
        s1 += __shfl_xor_sync(0xffffffffu, s1, 1);
        s1 += __shfl_xor_sync(0xffffffffu, s1, 2);
        s2 += __shfl_xor_sync(0xffffffffu, s2, 1);
        s2 += __shfl_xor_sync(0xffffffffu, s2, 2);
        if ((lane & 3) == 0) {
            red1[(rbase + t * 16) * 2 + nw] = s1;
            red1[(rbase + t * 16 + 8) * 2 + nw] = s2;
        }
    }
    __syncthreads();

    float mean1[2], mean2[2];
    #pragma unroll
    for (int t = 0; t < 2; t++) {
        float2 p1 = ((const float2*)red1)[rbase + t * 16];
        float2 p2 = ((const float2*)red1)[rbase + t * 16 + 8];
        mean1[t] = (p1.x + p1.y) * (1.0f / 128.0f);
        mean2[t] = (p2.x + p2.y) * (1.0f / 128.0f);
    }
    // pass 2: squared deviations
    #pragma unroll
    for (int t = 0; t < 2; t++) {
        float q1 = 0.f, q2 = 0.f;
        #pragma unroll
        for (int nt = 0; nt < 8; nt++) {
            const float* a4 = &acc[(t * 8 + nt) * 4];
            float d0 = a4[0] - mean1[t], d1 = a4[1] - mean1[t];
            float d2 = a4[2] - mean2[t], d3 = a4[3] - mean2[t];
            q1 += d0 * d0 + d1 * d1;
            q2 += d2 * d2 + d3 * d3;
        }
        q1 += __shfl_xor_sync(0xffffffffu, q1, 1);
        q1 += __shfl_xor_sync(0xffffffffu, q1, 2);
        q2 += __shfl_xor_sync(0xffffffffu, q2, 1);
        q2 += __shfl_xor_sync(0xffffffffu, q2, 2);
        if ((lane & 3) == 0) {
            red2[(rbase + t * 16) * 2 + nw] = q1;
            red2[(rbase + t * 16 + 8) * 2 + nw] = q2;
        }
    }
    __syncthreads();

    int ncol = nw * 64 + cq;
    #pragma unroll
    for (int t = 0; t < 2; t++) {
        float2 p1 = ((const float2*)red2)[rbase + t * 16];
        float2 p2 = ((const float2*)red2)[rbase + t * 16 + 8];
        float inv1 = rsqrtf((p1.x + p1.y) * (1.0f / 128.0f) + LN_EPS_SCALED);
        float inv2 = rsqrtf((p2.x + p2.y) * (1.0f / 128.0f) + LN_EPS_SCALED);
        size_t edge1 = (size_t)blockIdx.x * 256 + rbase + t * 16;
        size_t edge2 = edge1 + 8;
        #pragma unroll
        for (int nt = 0; nt < 8; nt++) {
            const float* a4 = &acc[(t * 8 + nt) * 4];
            int n0 = ncol + nt * 8;
            float2 gg = *(const float2*)(ln_gamma + n0);
            float2 bb = *(const float2*)(ln_beta + n0);
            float2 o1, o2;
            o1.x = (a4[0] - mean1[t]) * inv1 * gg.x + bb.x;
            o1.y = (a4[1] - mean1[t]) * inv1 * gg.y + bb.y;
            o2.x = (a4[2] - mean2[t]) * inv2 * gg.x + bb.x;
            o2.y = (a4[3] - mean2[t]) * inv2 * gg.y + bb.y;
            *(float2*)(outE + edge1 * 128 + n0) = o1;
            *(float2*)(outE + edge2 * 128 + n0) = o2;
        }
    }
}

// ---------------------------------------------------------------------------
// Launch. Input order: 0:X 1:mask 2:residue_idx 3:S 4:SSE3 5:SSE8 6:W_pos
// 7:b_pos 8:W_edge 9:ln_gamma 10:ln_beta.
// Output: E (f32, B*L*K*128) then E_idx as f32 (B*L*K).
// ---------------------------------------------------------------------------
extern "C" void kernel_launch(void* const* d_in, const int* in_sizes, int n_in,
                              void* d_out, int out_size) {
    const float* X        = (const float*)d_in[0];
    const int*   res_idx  = (const int*)  d_in[2];
    const float* W_pos    = (const float*)d_in[6];
    const float* b_pos    = (const float*)d_in[7];
    const float* W_edge   = (const float*)d_in[8];
    const float* ln_gamma = (const float*)d_in[9];
    const float* ln_beta  = (const float*)d_in[10];

    float* outE = (float*)d_out;
    int write_idx = (size_t)out_size >= E_ELEMS + (size_t)NEDGE;
    float* idx_out_f = write_idx ? outE + E_ELEMS : nullptr;

    cudaFuncSetAttribute(edge_hmma_kernel,
                         cudaFuncAttributeMaxDynamicSharedMemorySize, SM_TOTAL);
    cudaFuncSetAttribute(topk_kernel,
                         cudaFuncAttributeMaxDynamicSharedMemorySize, 65536);

    int prep_total = BB * LL + 128 * 416;   // 61440
    prep_fused_kernel<<<(prep_total + 255) / 256, 256>>>(X, W_edge);
    topk_kernel<<<BB * LL / 16, 128, 65536>>>(idx_out_f, write_idx);
    edge_hmma_kernel<<<NEDGE / 256, 512, SM_TOTAL>>>(
        res_idx, W_pos, b_pos, ln_gamma, ln_beta, outE);
}

// round 17
// speedup vs baseline: 1.0625x; 1.0625x over previous
#include <cuda_runtime.h>
#include <cuda_bf16.h>
#include <cuda_fp16.h>
#include <cstdint>

// Problem constants
#define BB   8
#define LL   1024
#define KNB  30
#define NUM_RBF 16
#define NPOS 16
#define MAXREL 32
#define EDGE 128
#define EDGE_IN (NPOS + NUM_RBF * 25)   // 416 = 26 * 16
#define NEDGE (BB * LL * KNB)           // 245760
#define E_ELEMS ((size_t)NEDGE * EDGE)  // 31457280
#define NKSTEP 26
#define WSCALE 32.0f                    // B pre-scale (avoids fp16 subnormals)
// LayerNorm is scale-invariant: fold 32^2 into eps instead of un-scaling acc.
#define LN_EPS_SCALED (1e-5f * 1024.0f)
#define RBF_A (-0.92332481f)            // -0.64 * log2(e)
#define RBF_D 1.33333337f

__constant__ int cPI[25] = {0,1,2,3,4,0,0,0,0,1,1,1,4,4,3,1,2,3,4,2,3,4,2,3,2};
__constant__ int cPJ[25] = {0,1,2,3,4,1,2,3,4,2,3,4,2,3,2,0,0,0,0,1,1,1,4,4,3};

// Scratch (static __device__ — no allocations allowed)
__device__ float4 g_atoms[BB * LL * 5];   // [Ca, N, C, O, Cb] per residue
__device__ float4 g_ca[BB * LL];
__device__ int    g_eidx[NEDGE];
// (W_edge*32)^T fp16: [n=128][k=416]  (row = 832 B = 52 uint4)
__device__ __align__(16) __half g_Bt[128 * 416];

// ---------------------------------------------------------------------------
// Small helpers
// ---------------------------------------------------------------------------
__device__ __forceinline__ uint32_t smem_u32(const void* p) {
    uint32_t a;
    asm("{ .reg .u64 t; cvta.to.shared.u64 t, %1; cvt.u32.u64 %0, t; }"
        : "=r"(a) : "l"(p));
    return a;
}
__device__ __forceinline__ uint32_t pack_f16x2(float f0, float f1) {
    uint32_t r;
    asm("cvt.rn.f16x2.f32 %0, %1, %2;" : "=r"(r) : "f"(f1), "f"(f0));
    return r;  // lo half = f0, hi half = f1
}
__device__ __forceinline__ float ex2f(float x) {
    float r;
    asm("ex2.approx.f32 %0, %1;" : "=f"(r) : "f"(x));
    return r;
}
__device__ __forceinline__ void mma16816(float* d, const uint32_t* a,
                                         const uint32_t* b) {
    asm volatile(
        "mma.sync.aligned.m16n8k16.row.col.f32.f16.f16.f32 "
        "{%0,%1,%2,%3}, {%4,%5,%6,%7}, {%8,%9}, {%0,%1,%2,%3};"
        : "+f"(d[0]), "+f"(d[1]), "+f"(d[2]), "+f"(d[3])
        : "r"(a[0]), "r"(a[1]), "r"(a[2]), "r"(a[3]), "r"(b[0]), "r"(b[1]));
}
__device__ __forceinline__ void ldsm4(uint32_t* r, uint32_t addr) {
    asm volatile(
        "ldmatrix.sync.aligned.m8n8.x4.shared.b16 {%0,%1,%2,%3}, [%4];"
        : "=r"(r[0]), "=r"(r[1]), "=r"(r[2]), "=r"(r[3]) : "r"(addr));
}
__device__ __forceinline__ unsigned long long kmin64(unsigned long long a,
                                                     unsigned long long b) {
    return a < b ? a : b;
}

// ---------------------------------------------------------------------------
// Kernel A (fused): prep (atom table) + bprep ((W*32)^T fp16).
// ---------------------------------------------------------------------------
__global__ void prep_fused_kernel(const float* __restrict__ X,
                                  const float* __restrict__ W_edge) {
    int idx = blockIdx.x * blockDim.x + threadIdx.x;
    if (idx < BB * LL) {
        int t = idx;
        const float* x = X + (size_t)t * 12;
        float Nx = x[0], Ny = x[1], Nz = x[2];
        float Ax = x[3], Ay = x[4], Az = x[5];
        float Cx = x[6], Cy = x[7], Cz = x[8];
        float Ox = x[9], Oy = x[10], Oz = x[11];
        float bx = Ax - Nx, by = Ay - Ny, bz = Az - Nz;
        float cx = Cx - Ax, cy = Cy - Ay, cz = Cz - Az;
        float ax = by * cz - bz * cy;
        float ay = bz * cx - bx * cz;
        float az = bx * cy - by * cx;
        float Bx = -0.58273431f * ax + 0.56802827f * bx - 0.54067466f * cx + Ax;
        float By = -0.58273431f * ay + 0.56802827f * by - 0.54067466f * cy + Ay;
        float Bz = -0.58273431f * az + 0.56802827f * bz - 0.54067466f * cz + Az;
        g_atoms[t * 5 + 0] = make_float4(Ax, Ay, Az, 0.f);
        g_atoms[t * 5 + 1] = make_float4(Nx, Ny, Nz, 0.f);
        g_atoms[t * 5 + 2] = make_float4(Cx, Cy, Cz, 0.f);
        g_atoms[t * 5 + 3] = make_float4(Ox, Oy, Oz, 0.f);
        g_atoms[t * 5 + 4] = make_float4(Bx, By, Bz, 0.f);
        g_ca[t] = make_float4(Ax, Ay, Az, 0.f);
    } else {
        int w = idx - BB * LL;
        if (w < 128 * 416) {
            int n = w / 416;
            int k = w - n * 416;
            float v = W_edge[k * 128 + n] * WSCALE;
            g_Bt[(size_t)n * 416 + k] = __float2half_rn(v);
        }
    }
}

// ---------------------------------------------------------------------------
// Kernel B: top-30 nearest neighbors (exact JAX tie-breaking).
// 2 rows per warp (same batch -> shared cj loads, 2x ILP on shuffle chains).
// Hierarchical: register-resident 32 group minima (lane g holds group g);
// each round reduces the 32 minima, then rescans only the losing group.
// Keys bank-XOR-swizzled: element j at word (j & ~31) | ((j ^ (j>>5)) & 31).
// ---------------------------------------------------------------------------
__global__ void topk_kernel(float* __restrict__ idx_out_f, int write_idx_f) {
    __shared__ __align__(16) uint32_t keys[8][LL];   // 32 KB: [warp*2+r][j]
    int tid = threadIdx.x;
    int warp = tid >> 5;
    int lane = tid & 31;
    int row0 = (blockIdx.x * 4 + warp) * 2;          // rows row0, row0+1 (same batch)
    int b = row0 >> 10;
    int base = b * LL;
    float4 c0 = g_ca[row0];
    float4 c1 = g_ca[row0 + 1];
    uint32_t* k0 = keys[warp * 2];
    uint32_t* k1 = keys[warp * 2 + 1];

    // fill keys (swizzled), sharing the cj load across both rows
    #pragma unroll 4
    for (int c = 0; c < 32; c++) {
        int j = c * 32 + lane;
        float4 cj = g_ca[base + j];
        float dx0 = c0.x - cj.x, dy0 = c0.y - cj.y, dz0 = c0.z - cj.z;
        float dx1 = c1.x - cj.x, dy1 = c1.y - cj.y, dz1 = c1.z - cj.z;
        float d0 = sqrtf(dx0 * dx0 + dy0 * dy0 + dz0 * dz0 + 1e-6f);
        float d1 = sqrtf(dx1 * dx1 + dy1 * dy1 + dz1 * dz1 + 1e-6f);
        int sw = c * 32 + ((lane ^ c) & 31);
        k0[sw] = __float_as_uint(d0);
        k1[sw] = __float_as_uint(d1);
    }
    __syncwarp();

    // group minima in registers: lane owns group g = lane (elems j = i*32+lane)
    unsigned long long gm0, gm1;
    {
        uint32_t v0 = ~0u, v1 = ~0u;
        int j0 = 0, j1 = 0;
        #pragma unroll 4
        for (int i = 0; i < 32; i++) {
            int sw = i * 32 + ((lane ^ i) & 31);
            uint32_t a0 = k0[sw], a1 = k1[sw];
            if (a0 < v0) { v0 = a0; j0 = i * 32 + lane; }
            if (a1 < v1) { v1 = a1; j1 = i * 32 + lane; }
        }
        gm0 = ((unsigned long long)v0 << 32) | (unsigned)j0;
        gm1 = ((unsigned long long)v1 << 32) | (unsigned)j1;
    }

    for (int kk = 0; kk < KNB; kk++) {
        unsigned long long b0 = gm0, b1 = gm1;
        #pragma unroll
        for (int off = 16; off; off >>= 1) {
            b0 = kmin64(b0, __shfl_xor_sync(0xffffffffu, b0, off));
            b1 = kmin64(b1, __shfl_xor_sync(0xffffffffu, b1, off));
        }
        unsigned j0 = (unsigned)(b0 & 0xffffffffu);
        unsigned j1 = (unsigned)(b1 & 0xffffffffu);
        if (lane == 0) {
            g_eidx[row0 * KNB + kk] = (int)j0;
            g_eidx[(row0 + 1) * KNB + kk] = (int)j1;
            if (write_idx_f) {
                idx_out_f[row0 * KNB + kk] = (float)j0;
                idx_out_f[(row0 + 1) * KNB + kk] = (float)j1;
            }
            k0[(j0 & ~31u) | ((j0 ^ (j0 >> 5)) & 31u)] = ~0u;
            k1[(j1 & ~31u) | ((j1 ^ (j1 >> 5)) & 31u)] = ~0u;
        }
        __syncwarp();
        // rescan losing groups: lane i holds element i*32 + g
        int g0 = j0 & 31, g1 = j1 & 31;
        uint32_t v0 = k0[lane * 32 + ((g0 ^ lane) & 31)];
        uint32_t v1 = k1[lane * 32 + ((g1 ^ lane) & 31)];
        unsigned long long c0r =
            ((unsigned long long)v0 << 32) | (unsigned)(lane * 32 + g0);
        unsigned long long c1r =
            ((unsigned long long)v1 << 32) | (unsigned)(lane * 32 + g1);
        #pragma unroll
        for (int off = 16; off; off >>= 1) {
            c0r = kmin64(c0r, __shfl_xor_sync(0xffffffffu, c0r, off));
            c1r = kmin64(c1r, __shfl_xor_sync(0xffffffffu, c1r, off));
        }
        if (lane == g0) gm0 = c0r;
        if (lane == g1) gm1 = c1r;
        __syncwarp();
    }
}

// ---------------------------------------------------------------------------
// Kernel C: HMMA (mma.sync fp16) edge GEMM + LayerNorm.
// CTA: 512 threads / 16 warps in an 8(M)x2(N) grid, M=256 edges per CTA.
// Warp tile: M=32 (2 m16 tiles, B fragments reused) x N=64 (8 n8 tiles).
// Full B (K=416) resident in SMEM, row stride 848 B (conflict-free ldsm).
// RBF via canonical ex2 form: f = ex2(a*d^2 + b_k*d + c_k).
// SMEM: Bs[128 n][848 B rows]                                 108544
//       sdist[256][25] f32 (reused for LN reductions)          25600
//       spos [256][16] f32                                     16384
// ---------------------------------------------------------------------------
#define SM_BS   0
#define SM_DIST 108544
#define SM_POS  134144
#define SM_TOTAL 150528

__global__ __launch_bounds__(512, 1) void edge_hmma_kernel(
    const int* __restrict__ res_idx,
    const float* __restrict__ W_pos,
    const float* __restrict__ b_pos,
    const float* __restrict__ ln_gamma,
    const float* __restrict__ ln_beta,
    float* __restrict__ outE) {

    extern __shared__ __align__(16) char smem[];
    uint32_t sbase = smem_u32(smem);
    int tid = threadIdx.x;
    int wid = tid >> 5;
    int lane = tid & 31;
    int mw = wid >> 1;        // 0..7  -> M slice of 32
    int nw = wid & 1;         // 0..1  -> N slice of 64

    float* sdist = (float*)(smem + SM_DIST);
    float* spos  = (float*)(smem + SM_POS);

    // ---- load full B: 128 rows x 52 uint4 = 6656 = 512*13 ----
    {
        const uint4* src = (const uint4*)g_Bt;
        #pragma unroll
        for (int it = 0; it < 13; it++) {
            int idx = tid + it * 512;
            int n = idx / 52;
            int col = idx - n * 52;
            uint4 v = src[n * 52 + col];
            *(uint4*)(smem + SM_BS + n * 848 + col * 16) = v;
        }
    }

    // ---- per-edge setup (threads 0..255) ----
    if (tid < 256) {
        int e = blockIdx.x * 256 + tid;
        int row = e / KNB;
        int b = row >> 10;
        int j = g_eidx[e];
        float4 pa[5], pb[5];
        #pragma unroll
        for (int a = 0; a < 5; a++) {
            pa[a] = g_atoms[row * 5 + a];
            pb[a] = g_atoms[(b * LL + j) * 5 + a];
        }
        #pragma unroll
        for (int p = 0; p < 25; p++) {
            float4 u = pa[cPI[p]], v = pb[cPJ[p]];
            float dx = u.x - v.x, dy = u.y - v.y, dz = u.z - v.z;
            sdist[tid * 25 + p] = sqrtf(dx * dx + dy * dy + dz * dz + 1e-6f);
        }
        int off = res_idx[row] - res_idx[b * LL + j];
        int dpos = off + MAXREL;
        dpos = dpos < 0 ? 0 : (dpos > 2 * MAXREL ? 2 * MAXREL : dpos);
        #pragma unroll
        for (int t = 0; t < NPOS; t++)
            spos[tid * 16 + t] = W_pos[dpos * NPOS + t] + b_pos[t];
    }
    __syncthreads();

    // ---- per-lane constants for A-fragment feature generation ----
    int rq = lane >> 2;                    // 0..7
    int rbase = mw * 32 + rq;              // local edge row (mtile 0, first of pair)
    int cq = (lane & 3) * 2;               // k-col within kstep
    float mu0 = 2.0f + (float)cq * RBF_D;
    float mu1 = mu0 + RBF_D;
    float mu8 = mu0 + 8.0f * RBF_D;
    float mu9 = mu0 + 9.0f * RBF_D;
    float bb0 = -2.0f * RBF_A * mu0, cc0 = RBF_A * mu0 * mu0;
    float bb1 = -2.0f * RBF_A * mu1, cc1 = RBF_A * mu1 * mu1;
    float bb8 = -2.0f * RBF_A * mu8, cc8 = RBF_A * mu8 * mu8;
    float bb9 = -2.0f * RBF_A * mu9, cc9 = RBF_A * mu9 * mu9;

    // B fragment base: warp covers n rows [nw*64, nw*64+64)
    uint32_t b_base = sbase + SM_BS + (uint32_t)(nw * 64) * 848 +
        (uint32_t)((lane & 7) + ((lane >> 4) << 3)) * 848 +
        (uint32_t)((lane >> 3) & 1) * 16;

    float acc[64];   // [t(2)][nt(8)][4]
    #pragma unroll
    for (int i = 0; i < 64; i++) acc[i] = 0.f;

    // ---- ks = 0 peeled: pos features ----
    {
        uint32_t bh[16];
        #pragma unroll
        for (int g = 0; g < 4; g++)
            ldsm4(&bh[g * 4], b_base + g * 16 * 848);
        uint32_t ah[2][4];
        #pragma unroll
        for (int t = 0; t < 2; t++) {
            int eA = rbase + t * 16;
            int eB = eA + 8;
            ah[t][0] = pack_f16x2(spos[eA * 16 + cq],     spos[eA * 16 + cq + 1]);
            ah[t][1] = pack_f16x2(spos[eB * 16 + cq],     spos[eB * 16 + cq + 1]);
            ah[t][2] = pack_f16x2(spos[eA * 16 + cq + 8], spos[eA * 16 + cq + 9]);
            ah[t][3] = pack_f16x2(spos[eB * 16 + cq + 8], spos[eB * 16 + cq + 9]);
        }
        #pragma unroll
        for (int t = 0; t < 2; t++) {
            #pragma unroll
            for (int nt = 0; nt < 8; nt++)
                mma16816(&acc[(t * 8 + nt) * 4], ah[t],
                         &bh[(nt >> 1) * 4 + (nt & 1) * 2]);
        }
    }

    // ---- main K loop: ks = 1..25 (RBF features only) ----
    #pragma unroll 1
    for (int ks = 1; ks < NKSTEP; ks++) {
        uint32_t bh[16];
        uint32_t bks = b_base + (uint32_t)ks * 32;
        #pragma unroll
        for (int g = 0; g < 4; g++)
            ldsm4(&bh[g * 4], bks + g * 16 * 848);

        uint32_t ah[2][4];
        #pragma unroll
        for (int t = 0; t < 2; t++) {
            int eA = rbase + t * 16;
            int eB = eA + 8;
            float dA = sdist[eA * 25 + ks - 1];
            float dB = sdist[eB * 25 + ks - 1];
            float dA2 = dA * dA;
            float dB2 = dB * dB;
            float f0 = ex2f(fmaf(RBF_A, dA2, fmaf(bb0, dA, cc0)));
            float f1 = ex2f(fmaf(RBF_A, dA2, fmaf(bb1, dA, cc1)));
            float f2 = ex2f(fmaf(RBF_A, dB2, fmaf(bb0, dB, cc0)));
            float f3 = ex2f(fmaf(RBF_A, dB2, fmaf(bb1, dB, cc1)));
            float f4 = ex2f(fmaf(RBF_A, dA2, fmaf(bb8, dA, cc8)));
            float f5 = ex2f(fmaf(RBF_A, dA2, fmaf(bb9, dA, cc9)));
            float f6 = ex2f(fmaf(RBF_A, dB2, fmaf(bb8, dB, cc8)));
            float f7 = ex2f(fmaf(RBF_A, dB2, fmaf(bb9, dB, cc9)));
            ah[t][0] = pack_f16x2(f0, f1);
            ah[t][1] = pack_f16x2(f2, f3);
            ah[t][2] = pack_f16x2(f4, f5);
            ah[t][3] = pack_f16x2(f6, f7);
        }

        #pragma unroll
        for (int t = 0; t < 2; t++) {
            #pragma unroll
            for (int nt = 0; nt < 8; nt++)
                mma16816(&acc[(t * 8 + nt) * 4], ah[t],
                         &bh[(nt >> 1) * 4 + (nt & 1) * 2]);
        }
    }

    // ---- LayerNorm epilogue (scale-invariant: 32x fold into eps) ----
    __syncthreads();   // protect sdist reuse
    float* red1 = (float*)(smem + SM_DIST);          // [256][2] sums
    float* red2 = (float*)(smem + SM_DIST + 2048);   // [256][2] sq-sums

    // pass 1: sums
    #pragma unroll
    for (int t = 0; t < 2; t++) {
        float s1 = 0.f, s2 = 0.f;
        #pragma unroll
        for (int nt = 0; nt < 8; nt++) {
            const float* a4 = &acc[(t * 8 + nt) * 4];
            s1 += a4[0] + a4[1];
            s2 += a4[2] + a4[3];
        }
        s1 += __shfl_xor_sync(0xffffffffu, s1, 1);
        s1 += __shfl_xor_sync(0xffffffffu, s1, 2);
        s2 += __shfl_xor_sync(0xffffffffu, s2, 1);
        s2 += __shfl_xor_sync(0xffffffffu, s2, 2);
        if ((lane & 3) == 0) {
            red1[(rbase + t * 16) * 2 + nw] = s1;
            red1[(rbase + t * 16 + 8) * 2 + nw] = s2;
        }
    }
    __syncthreads();

    float mean1[2], mean2[2];
    #pragma unroll
    for (int t = 0; t < 2; t++) {
        float2 p1 = ((const float2*)red1)[rbase + t * 16];
        float2 p2 = ((const float2*)red1)[rbase + t * 16 + 8];
        mean1[t] = (p1.x + p1.y) * (1.0f / 128.0f);
        mean2[t] = (p2.x + p2.y) * (1.0f / 128.0f);
    }
    // pass 2: squared deviations
    #pragma unroll
    for (int t = 0; t < 2; t++) {
        float q1 = 0.f, q2 = 0.f;
        #pragma unroll
        for (int nt = 0; nt < 8; nt++) {
            const float* a4 = &acc[(t * 8 + nt) * 4];
            float d0 = a4[0] - mean1[t], d1 = a4[1] - mean1[t];
            float d2 = a4[2] - mean2[t], d3 = a4[3] - mean2[t];
            q1 += d0 * d0 + d1 * d1;
            q2 += d2 * d2 + d3 * d3;
        }
        q1 += __shfl_xor_sync(0xffffffffu, q1, 1);
        q1 += __shfl_xor_sync(0xffffffffu, q1, 2);
        q2 += __shfl_xor_sync(0xffffffffu, q2, 1);
        q2 += __shfl_xor_sync(0xffffffffu, q2, 2);
        if ((lane & 3) == 0) {
            red2[(rbase + t * 16) * 2 + nw] = q1;
            red2[(rbase + t * 16 + 8) * 2 + nw] = q2;
        }
    }
    __syncthreads();

    int ncol = nw * 64 + cq;
    #pragma unroll
    for (int t = 0; t < 2; t++) {
        float2 p1 = ((const float2*)red2)[rbase + t * 16];
        float2 p2 = ((const float2*)red2)[rbase + t * 16 + 8];
        float inv1 = rsqrtf((p1.x + p1.y) * (1.0f / 128.0f) + LN_EPS_SCALED);
        float inv2 = rsqrtf((p2.x + p2.y) * (1.0f / 128.0f) + LN_EPS_SCALED);
        size_t edge1 = (size_t)blockIdx.x * 256 + rbase + t * 16;
        size_t edge2 = edge1 + 8;
        #pragma unroll
        for (int nt = 0; nt < 8; nt++) {
            const float* a4 = &acc[(t * 8 + nt) * 4];
            int n0 = ncol + nt * 8;
            float2 gg = *(const float2*)(ln_gamma + n0);
            float2 bb = *(const float2*)(ln_beta + n0);
            float2 o1, o2;
            o1.x = (a4[0] - mean1[t]) * inv1 * gg.x + bb.x;
            o1.y = (a4[1] - mean1[t]) * inv1 * gg.y + bb.y;
            o2.x = (a4[2] - mean2[t]) * inv2 * gg.x + bb.x;
            o2.y = (a4[3] - mean2[t]) * inv2 * gg.y + bb.y;
            *(float2*)(outE + edge1 * 128 + n0) = o1;
            *(float2*)(outE + edge2 * 128 + n0) = o2;
        }
    }
}

// ---------------------------------------------------------------------------
// Launch. Input order: 0:X 1:mask 2:residue_idx 3:S 4:SSE3 5:SSE8 6:W_pos
// 7:b_pos 8:W_edge 9:ln_gamma 10:ln_beta.
// Output: E (f32, B*L*K*128) then E_idx as f32 (B*L*K).
// ---------------------------------------------------------------------------
extern "C" void kernel_launch(void* const* d_in, const int* in_sizes, int n_in,
                              void* d_out, int out_size) {
    const float* X        = (const float*)d_in[0];
    const int*   res_idx  = (const int*)  d_in[2];
    const float* W_pos    = (const float*)d_in[6];
    const float* b_pos    = (const float*)d_in[7];
    const float* W_edge   = (const float*)d_in[8];
    const float* ln_gamma = (const float*)d_in[9];
    const float* ln_beta  = (const float*)d_in[10];

    float* outE = (float*)d_out;
    int write_idx = (size_t)out_size >= E_ELEMS + (size_t)NEDGE;
    float* idx_out_f = write_idx ? outE + E_ELEMS : nullptr;

    cudaFuncSetAttribute(edge_hmma_kernel,
                         cudaFuncAttributeMaxDynamicSharedMemorySize, SM_TOTAL);

    int prep_total = BB * LL + 128 * 416;   // 61440
    prep_fused_kernel<<<(prep_total + 255) / 256, 256>>>(X, W_edge);
    topk_kernel<<<BB * LL / 8, 128>>>(idx_out_f, write_idx);
    edge_hmma_kernel<<<NEDGE / 256, 512, SM_TOTAL>>>(
        res_idx, W_pos, b_pos, ln_gamma, ln_beta, outE);
}